// round 11
// baseline (speedup 1.0000x reference)
#include <cuda_runtime.h>
#include <cuda_bf16.h>
#include <cstdint>

// ---------------------------------------------------------------------------
// SparseResNet on GB300 — Round 10: warp-specialized tcgen05 bf16x3 conv with
// pipelined cp.async gather. Warps 0-7 (256 thr) = producers (one-ahead
// cp.async, producer-only bar.sync + full[] arrive); warp 8 = pure MMA issuer
// (mb_wait full -> 24 MMAs -> commit done). No __syncthreads in the mainloop:
// the tcgen05 queue stall now overlaps the next gather (R9 left them serial).
// ---------------------------------------------------------------------------

#if defined(__CUDA_ARCH_FEAT_SM103_ALL) || defined(__CUDA_ARCH_FEAT_SM100_ALL) || \
    defined(__CUDA_ARCH_FEAT_SM101_ALL)
#define HAS_TC 1
#else
#define HAS_TC 0
#endif

#define M1 27648
#define M2 46080
#define MAXPART 192

// fp32 masters / scratch
__device__ float g_A[M1 * 128];
__device__ float g_B[M1 * 128];
__device__ float g_C[M1 * 128];
__device__ float g_D[M2 * 32];
__device__ float g_psum[MAXPART * 128];
__device__ float g_pssq[MAXPART * 128];

// split bf16 activations
__device__ __nv_bfloat16 g_xh[9216 * 256];
__device__ __nv_bfloat16 g_xl[9216 * 256];
__device__ __nv_bfloat16 g_Fh[M1 * 128];
__device__ __nv_bfloat16 g_Fl[M1 * 128];

// split + transposed weights: layout [k][cout][cin]
__device__ __nv_bfloat16 g_w1h[27 * 128 * 256];
__device__ __nv_bfloat16 g_w1l[27 * 128 * 256];
#define WB_SZ (27 * 128 * 128)
__device__ __nv_bfloat16 g_wbh[4 * WB_SZ];
__device__ __nv_bfloat16 g_wbl[4 * WB_SZ];
__device__ __nv_bfloat16 g_w2h[27 * 32 * 128];
__device__ __nv_bfloat16 g_w2l[27 * 32 * 128];

// ------------------------------ PTX helpers --------------------------------
__device__ __forceinline__ uint32_t smem_u32(const void* p) {
    uint32_t a;
    asm("{ .reg .u64 t; cvta.to.shared.u64 t, %1; cvt.u32.u64 %0, t; }"
        : "=r"(a) : "l"(p));
    return a;
}

// cp.async 16B with selectable src-size (0 => zero-fill). Ampere+, no 'a' gate.
__device__ __forceinline__ void cp16(uint32_t dst, const void* src, int sz) {
    asm volatile("cp.async.cg.shared.global [%0], [%1], 16, %2;"
                 :: "r"(dst), "l"(src), "r"(sz) : "memory");
}
#define CP_COMMIT() asm volatile("cp.async.commit_group;" ::: "memory")
#define CP_WAIT0()  asm volatile("cp.async.wait_group 0;" ::: "memory")
#define CP_WAIT1()  asm volatile("cp.async.wait_group 1;" ::: "memory")

#if HAS_TC
__device__ __forceinline__ uint32_t elect_one_pred() {
    uint32_t pred;
    asm volatile(
        "{\n\t.reg .pred p;\n\t"
        "elect.sync _|p, 0xFFFFFFFF;\n\t"
        "selp.b32 %0, 1, 0, p;\n\t}"
        : "=r"(pred));
    return pred;
}

#define TC_ALLOC(sa, n)                                                      \
    asm volatile("tcgen05.alloc.cta_group::1.sync.aligned.shared::cta.b32 [%0], %1;" \
                 :: "r"(sa), "r"((uint32_t)(n)) : "memory")
#define TC_DEALLOC(t, n)                                                     \
    asm volatile("tcgen05.dealloc.cta_group::1.sync.aligned.b32 %0, %1;"     \
                 :: "r"(t), "r"((uint32_t)(n)))
#define TC_COMMIT(mb)                                                        \
    asm volatile("tcgen05.commit.cta_group::1.mbarrier::arrive::one.shared::cluster.b64 [%0];" \
                 :: "r"(mb) : "memory")
#define TC_WAIT_LD() asm volatile("tcgen05.wait::ld.sync.aligned;" ::: "memory")
#define TC_FENCE_AFTER() asm volatile("tcgen05.fence::after_thread_sync;" ::: "memory")
#define FENCE_ASYNC() asm volatile("fence.proxy.async.shared::cta;" ::: "memory")

#define MB_INIT(a, c)                                                        \
    asm volatile("mbarrier.init.shared.b64 [%0], %1;" :: "r"(a), "r"((uint32_t)(c)) : "memory")
#define MB_INVAL(a)                                                          \
    asm volatile("mbarrier.inval.shared.b64 [%0];" :: "r"(a) : "memory")
#define MB_ARRIVE(a)                                                         \
    asm volatile("mbarrier.arrive.shared.b64 _, [%0];" :: "r"(a) : "memory")

__device__ __forceinline__ void mb_wait(uint32_t mbar, uint32_t parity) {
    uint32_t done;
    asm volatile(
        "{\n\t.reg .pred p;\n\t"
        "mbarrier.try_wait.parity.acquire.cta.shared::cta.b64 p, [%1], %2;\n\t"
        "selp.b32 %0, 1, 0, p;\n\t}"
        : "=r"(done) : "r"(mbar), "r"(parity) : "memory");
    if (!done) {
        asm volatile(
            "{\n\t.reg .pred P1;\n\t"
            "WL_%=:\n\t"
            "mbarrier.try_wait.parity.acquire.cta.shared::cta.b64 P1, [%0], %1, 0x989680;\n\t"
            "@P1 bra.uni WD_%=;\n\t"
            "bra.uni WL_%=;\n\t"
            "WD_%=:\n\t}"
            :: "r"(mbar), "r"(parity) : "memory");
    }
}

// SS-mode bf16 MMA, fp32 accumulate, cta_group::1
__device__ __forceinline__ void mma_bf16_ss(uint32_t d, uint64_t ad, uint64_t bd,
                                            uint32_t id, uint32_t en) {
    asm volatile(
        "{\n\t.reg .pred p;\n\t"
        "setp.ne.u32 p, %5, 0;\n\t"
        "tcgen05.mma.cta_group::1.kind::f16 [%0], %1, %2, %3, {%4, %4, %4, %4}, p;\n\t}"
        :: "r"(d), "l"(ad), "l"(bd), "r"(id), "r"(0u), "r"(en) : "memory");
}

__device__ __forceinline__ void tc_ld32(uint32_t* r, uint32_t ta) {
    asm volatile(
        "tcgen05.ld.sync.aligned.32x32b.x32.b32 "
        "{%0, %1, %2, %3, %4, %5, %6, %7, "
        " %8, %9, %10, %11, %12, %13, %14, %15, "
        " %16, %17, %18, %19, %20, %21, %22, %23, "
        " %24, %25, %26, %27, %28, %29, %30, %31}, [%32];"
        : "=r"(r[0]), "=r"(r[1]), "=r"(r[2]), "=r"(r[3]),
          "=r"(r[4]), "=r"(r[5]), "=r"(r[6]), "=r"(r[7]),
          "=r"(r[8]), "=r"(r[9]), "=r"(r[10]), "=r"(r[11]),
          "=r"(r[12]), "=r"(r[13]), "=r"(r[14]), "=r"(r[15]),
          "=r"(r[16]), "=r"(r[17]), "=r"(r[18]), "=r"(r[19]),
          "=r"(r[20]), "=r"(r[21]), "=r"(r[22]), "=r"(r[23]),
          "=r"(r[24]), "=r"(r[25]), "=r"(r[26]), "=r"(r[27]),
          "=r"(r[28]), "=r"(r[29]), "=r"(r[30]), "=r"(r[31])
        : "r"(ta));
}
#endif  // HAS_TC

#define SW128(o) ((o) ^ (((o) >> 3) & 0x70))

// SW128 K-major descriptor (validated: layout=2, ver=1, SBO=64, LBO=1)
#define DBASE ((2ull << 61) | (1ull << 46) | (64ull << 32) | (1ull << 16))
#define MKDESC(a) (DBASE | (uint64_t)((((a) >> 4)) & 0x3FFF))

// ---------------------------------------------------------------------------
// Warp-specialized tcgen05 implicit-gather conv. 2 M-tiles per CTA (256 rows),
// K chunked at 64, 288 threads: warps 0-7 = cp.async producers (one-ahead
// pipeline, reg-resident rulebook), warp 8 = MMA issuer. BN partials fused
// in epilogue.
// ---------------------------------------------------------------------------
template <int CIN, int COUT>
__global__ void __launch_bounds__(288, 1)
spconv_tc(const __nv_bfloat16* __restrict__ fh, const __nv_bfloat16* __restrict__ fl,
          const __nv_bfloat16* __restrict__ wh, const __nv_bfloat16* __restrict__ wl,
          const int* __restrict__ nb, float* __restrict__ out, int M) {
#if HAS_TC
    extern __shared__ __align__(16) char smem[];
    constexpr int A_T     = 128 * 128;
    constexpr int A_BYTES = 4 * A_T;
    constexpr int B_ONE   = COUT * 128;
    constexpr int STAGE   = A_BYTES + 2 * B_ONE;
    constexpr int CHUNKS  = CIN / 64;
    constexpr int NIT     = 27 * CHUNKS;
    constexpr int WITER   = COUT * 8 / 256;
    constexpr uint32_t IDESC =
        (1u << 4) | (1u << 7) | (1u << 10) | ((uint32_t)(COUT / 8) << 17) | (8u << 24);

    const int tid = threadIdx.x;
    const int wid = tid >> 5;
    const int lid = tid & 31;
    const int m0  = blockIdx.x * 256;

    uint32_t b32 = smem_u32(smem);
    uint32_t pad = (1024u - (b32 & 1023u)) & 1023u;
    char* ctrl   = smem + pad;
    char* tiles  = ctrl + 2048;
    uint32_t ctrl_a  = b32 + pad;
    uint32_t tiles_a = ctrl_a + 2048;
    uint32_t mb_done[2] = {ctrl_a + 8,  ctrl_a + 16};
    uint32_t mb_full[2] = {ctrl_a + 24, ctrl_a + 32};

    if (wid == 0) TC_ALLOC(ctrl_a, 256);
    if (tid == 0) {
        MB_INIT(mb_done[0], 1); MB_INIT(mb_done[1], 1);
        MB_INIT(mb_full[0], 1); MB_INIT(mb_full[1], 1);
    }
    __syncthreads();
    const uint32_t tmem = *(volatile uint32_t*)ctrl;

    if (wid < 8) {
        // ---------------- producers (256 threads): pipelined cp.async -------
        int gro[8];
        uint32_t adst[8];
        uint32_t asrcseg[8];
#pragma unroll
        for (int i = 0; i < 8; ++i) {
            int t = tid + 256 * i;
            int tile = t >> 10, row = (t >> 3) & 127, seg = t & 7;
            gro[i]     = m0 + tile * 128 + row;
            adst[i]    = tile * (2 * A_T) + SW128(row * 128 + seg * 16);
            asrcseg[i] = seg * 16;
        }
        int ridx[8];
#pragma unroll
        for (int i = 0; i < 8; ++i) ridx[i] = nb[gro[i]];   // k = 0

        auto issue_gather = [&](uint32_t sbase, int k, int c0) {
#pragma unroll
            for (int i = 0; i < 8; ++i) {
                int idx = ridx[i];
                int sz  = (idx >= 0) ? 16 : 0;
                int ri  = (idx >= 0) ? idx : 0;
                const char* ph = (const char*)(fh + (size_t)ri * CIN + c0) + asrcseg[i];
                const char* pl = (const char*)(fl + (size_t)ri * CIN + c0) + asrcseg[i];
                uint32_t dst = sbase + adst[i];
                cp16(dst, ph, sz);
                cp16(dst + A_T, pl, sz);
            }
#pragma unroll
            for (int i = 0; i < WITER; ++i) {
                int t = tid + 256 * i;
                int row = t >> 3, seg = t & 7;
                const char* ph = (const char*)(wh + ((size_t)k * COUT + row) * CIN + c0) + seg * 16;
                const char* pl = (const char*)(wl + ((size_t)k * COUT + row) * CIN + c0) + seg * 16;
                uint32_t so = SW128(row * 128 + seg * 16);
                uint32_t dst = sbase + A_BYTES + so;
                cp16(dst, ph, 16);
                cp16(dst + B_ONE, pl, 16);
            }
            CP_COMMIT();
        };

        issue_gather(tiles_a, 0, 0);   // prologue: iteration 0 into buffer 0

        for (int it = 0; it < NIT; ++it) {
            if (it + 1 < NIT) {
                const int k1 = (it + 1) / CHUNKS;
                const int c1 = ((it + 1) % CHUNKS) * 64;
                if ((it + 1) % CHUNKS == 0) {
#pragma unroll
                    for (int i = 0; i < 8; ++i) ridx[i] = nb[k1 * M + gro[i]];
                }
                if (it >= 1) mb_wait(mb_done[(it + 1) & 1], (uint32_t)(((it - 1) >> 1) & 1));
                issue_gather(tiles_a + (uint32_t)(((it + 1) & 1) * STAGE), k1, c1);
                CP_WAIT1();
            } else {
                CP_WAIT0();
            }
            FENCE_ASYNC();
            asm volatile("bar.sync 1, 256;" ::: "memory");
            if (tid == 0) MB_ARRIVE(mb_full[it & 1]);
        }
    } else {
        // ---------------- consumer (warp 8): pure MMA issuer ----------------
        for (int it = 0; it < NIT; ++it) {
            const int b = it & 1;
            mb_wait(mb_full[b], (uint32_t)((it >> 1) & 1));
            if (elect_one_pred()) {
                const uint32_t sbase = tiles_a + (uint32_t)(b * STAGE);
                uint64_t bdh = MKDESC(sbase + A_BYTES);
                uint64_t bdl = MKDESC(sbase + A_BYTES + B_ONE);
#pragma unroll
                for (int tile = 0; tile < 2; ++tile) {
                    uint64_t adh = MKDESC(sbase + tile * (2 * A_T));
                    uint64_t adl = MKDESC(sbase + tile * (2 * A_T) + A_T);
                    uint32_t dt  = tmem + tile * 128;
#pragma unroll
                    for (int s = 0; s < 4; ++s) {
                        mma_bf16_ss(dt, adh + 2 * s, bdh + 2 * s, IDESC,
                                    (it == 0 && s == 0) ? 0u : 1u);
                        mma_bf16_ss(dt, adh + 2 * s, bdl + 2 * s, IDESC, 1u);
                        mma_bf16_ss(dt, adl + 2 * s, bdh + 2 * s, IDESC, 1u);
                    }
                }
                TC_COMMIT(mb_done[b]);
            }
        }
    }

    // drain both buffers' last MMA commits
    {
        uint32_t up = (uint32_t)((NIT / 2 - 1) & 1);
        mb_wait(mb_done[0], up);
        mb_wait(mb_done[1], up);
    }
    __syncthreads();
    TC_FENCE_AFTER();

    // epilogue (warps 0-7): store D + per-CTA BN partials
    float* ssum = reinterpret_cast<float*>(tiles);
    float* ssq  = ssum + 8 * COUT;
    if (wid < 8) {
        int tile = wid >> 2, sub = wid & 3;
        int row  = m0 + tile * 128 + sub * 32 + lid;
        uint32_t tbase = tmem + tile * 128;
        float* op = out + (size_t)row * COUT;
        uint32_t r[32];
#pragma unroll
        for (int c = 0; c < COUT; c += 32) {
            tc_ld32(r, tbase + c);
            TC_WAIT_LD();
#pragma unroll
            for (int j = 0; j < 32; j += 4)
                *reinterpret_cast<float4*>(op + c + j) =
                    make_float4(__uint_as_float(r[j]), __uint_as_float(r[j + 1]),
                                __uint_as_float(r[j + 2]), __uint_as_float(r[j + 3]));
#pragma unroll
            for (int j = 0; j < 32; ++j) {
                float v = __uint_as_float(r[j]);
                float s = v, q = v * v;
#pragma unroll
                for (int o = 16; o > 0; o >>= 1) {
                    s += __shfl_xor_sync(0xFFFFFFFFu, s, o);
                    q += __shfl_xor_sync(0xFFFFFFFFu, q, o);
                }
                if (lid == 0) { ssum[wid * COUT + c + j] = s; ssq[wid * COUT + c + j] = q; }
            }
        }
    }
    __syncthreads();
    if (tid < COUT) {
        float s = 0.f, q = 0.f;
#pragma unroll
        for (int w = 0; w < 8; ++w) { s += ssum[w * COUT + tid]; q += ssq[w * COUT + tid]; }
        g_psum[blockIdx.x * COUT + tid] = s;
        g_pssq[blockIdx.x * COUT + tid] = q;
    }

    __syncthreads();
    if (tid == 0) {
        MB_INVAL(mb_done[0]); MB_INVAL(mb_done[1]);
        MB_INVAL(mb_full[0]); MB_INVAL(mb_full[1]);
    }
    if (wid == 0) TC_DEALLOC(tmem, 256);
#else
    // --- SIMT fallback (non-'a' PTX stage only; correct, slow) ---
    const int m0 = blockIdx.x * 256;
    for (int o = threadIdx.x; o < 256 * COUT; o += (int)blockDim.x) {
        int r = o / COUT, c = o % COUT;
        float acc = 0.f;
        for (int k = 0; k < 27; ++k) {
            int idx = nb[k * M + m0 + r];
            if (idx < 0) continue;
            const __nv_bfloat16* ph = fh + (size_t)idx * CIN;
            const __nv_bfloat16* pl = fl + (size_t)idx * CIN;
            const __nv_bfloat16* qh = wh + ((size_t)k * COUT + c) * CIN;
            const __nv_bfloat16* ql = wl + ((size_t)k * COUT + c) * CIN;
            for (int ci = 0; ci < CIN; ++ci) {
                float a = __bfloat162float(ph[ci]) + __bfloat162float(pl[ci]);
                float w = __bfloat162float(qh[ci]) + __bfloat162float(ql[ci]);
                acc = fmaf(a, w, acc);
            }
        }
        out[(size_t)(m0 + r) * COUT + c] = acc;
    }
    __syncthreads();
    if (threadIdx.x < COUT) {
        float s = 0.f, q = 0.f;
        for (int r = 0; r < 256; ++r) {
            float v = out[(size_t)(m0 + r) * COUT + threadIdx.x];
            s += v; q += v * v;
        }
        g_psum[blockIdx.x * COUT + threadIdx.x] = s;
        g_pssq[blockIdx.x * COUT + threadIdx.x] = q;
    }
#endif
}

// --------------------- fused prep: split x + all weights -------------------
__global__ void prep_all(const float* __restrict__ x,
                         const float* w1, const float* w11, const float* w12,
                         const float* w21, const float* w22, const float* w2,
                         __nv_bfloat16* xh, __nv_bfloat16* xl,
                         __nv_bfloat16* w1h, __nv_bfloat16* w1l,
                         __nv_bfloat16* wbh, __nv_bfloat16* wbl,
                         __nv_bfloat16* w2h, __nv_bfloat16* w2l) {
    const int NX = 9216 * 256;
    const int N1 = 27 * 256 * 128;
    const int NB = 27 * 128 * 128;
    const int N2 = 27 * 128 * 32;
    const int TOT = NX + N1 + 4 * NB + N2;
    for (int t = blockIdx.x * blockDim.x + threadIdx.x; t < TOT;
         t += gridDim.x * blockDim.x) {
        if (t < NX) {
            float v = x[t];
            __nv_bfloat16 h = __float2bfloat16_rn(v);
            xh[t] = h;
            xl[t] = __float2bfloat16_rn(v - __bfloat162float(h));
            continue;
        }
        int u = t - NX;
        const float* src; __nv_bfloat16 *oh, *ol; int CI, CO, li;
        if (u < N1) { src = w1; oh = w1h; ol = w1l; CI = 256; CO = 128; li = u; }
        else if (u < N1 + 4 * NB) {
            int q = (u - N1) / NB, r = (u - N1) % NB;
            src = (q == 0) ? w11 : (q == 1) ? w12 : (q == 2) ? w21 : w22;
            oh = wbh + q * NB; ol = wbl + q * NB; CI = 128; CO = 128; li = r;
        } else { src = w2; oh = w2h; ol = w2l; CI = 128; CO = 32; li = u - N1 - 4 * NB; }
        int k = li / (CI * CO), r = li % (CI * CO);
        int ci = r / CO, co = r % CO;
        float v = src[li];
        __nv_bfloat16 h = __float2bfloat16_rn(v);
        int o = (k * CO + co) * CI + ci;
        oh[o] = h;
        ol[o] = __float2bfloat16_rn(v - __bfloat162float(h));
    }
}

// ---------------- fused BN finalize + normalize (+res)(+relu)(+split) ------
template <int C, bool RELU, bool RES, bool SPLIT, bool WF32>
__global__ void bn_apply(const float* __restrict__ f, const float* __restrict__ res,
                         const float* __restrict__ g, const float* __restrict__ b,
                         float* __restrict__ out, __nv_bfloat16* __restrict__ oh,
                         __nv_bfloat16* __restrict__ ol, int M, int npart) {
    __shared__ float sc[C], sh[C];
    for (int c = threadIdx.x; c < C; c += blockDim.x) {
        float s = 0.f, ss = 0.f;
        for (int i = 0; i < npart; ++i) { s += g_psum[i * C + c]; ss += g_pssq[i * C + c]; }
        float inv_m = 1.f / (float)M;
        float mu  = s * inv_m;
        float var = ss * inv_m - mu * mu;
        float scv = g[c] * rsqrtf(var + 1e-5f);
        sc[c] = scv;
        sh[c] = b[c] - mu * scv;
    }
    __syncthreads();
    int total4 = M * C / 4;
    for (int i = blockIdx.x * blockDim.x + threadIdx.x; i < total4;
         i += gridDim.x * blockDim.x) {
        float4 v = reinterpret_cast<const float4*>(f)[i];
        int c0 = (i * 4) % C;
        v.x = v.x * sc[c0 + 0] + sh[c0 + 0];
        v.y = v.y * sc[c0 + 1] + sh[c0 + 1];
        v.z = v.z * sc[c0 + 2] + sh[c0 + 2];
        v.w = v.w * sc[c0 + 3] + sh[c0 + 3];
        if (RES) {
            float4 r = reinterpret_cast<const float4*>(res)[i];
            v.x += r.x; v.y += r.y; v.z += r.z; v.w += r.w;
        }
        if (RELU) {
            v.x = fmaxf(v.x, 0.f); v.y = fmaxf(v.y, 0.f);
            v.z = fmaxf(v.z, 0.f); v.w = fmaxf(v.w, 0.f);
        }
        if (WF32) reinterpret_cast<float4*>(out)[i] = v;
        if (SPLIT) {
            __nv_bfloat16 hx = __float2bfloat16_rn(v.x), hy = __float2bfloat16_rn(v.y);
            __nv_bfloat16 hz = __float2bfloat16_rn(v.z), hw = __float2bfloat16_rn(v.w);
            __nv_bfloat162* oh2 = reinterpret_cast<__nv_bfloat162*>(oh);
            __nv_bfloat162* ol2 = reinterpret_cast<__nv_bfloat162*>(ol);
            oh2[2 * i]     = __nv_bfloat162(hx, hy);
            oh2[2 * i + 1] = __nv_bfloat162(hz, hw);
            ol2[2 * i]     = __nv_bfloat162(__float2bfloat16_rn(v.x - __bfloat162float(hx)),
                                            __float2bfloat16_rn(v.y - __bfloat162float(hy)));
            ol2[2 * i + 1] = __nv_bfloat162(__float2bfloat16_rn(v.z - __bfloat162float(hz)),
                                            __float2bfloat16_rn(v.w - __bfloat162float(hw)));
        }
    }
}

// ---------------------------------------------------------------------------
extern "C" void kernel_launch(void* const* d_in, const int* in_sizes, int n_in,
                              void* d_out, int out_size) {
    (void)in_sizes; (void)n_in; (void)out_size;

    const float* x    = (const float*)d_in[0];
    const float* w_s1 = (const float*)d_in[1];
    const float* g_s1 = (const float*)d_in[2];
    const float* b_s1 = (const float*)d_in[3];
    const float* w11  = (const float*)d_in[4];
    const float* g11  = (const float*)d_in[5];
    const float* b11  = (const float*)d_in[6];
    const float* w12  = (const float*)d_in[7];
    const float* g12  = (const float*)d_in[8];
    const float* b12  = (const float*)d_in[9];
    const float* w21  = (const float*)d_in[10];
    const float* g21  = (const float*)d_in[11];
    const float* b21  = (const float*)d_in[12];
    const float* w22  = (const float*)d_in[13];
    const float* g22  = (const float*)d_in[14];
    const float* b22  = (const float*)d_in[15];
    const float* w_s2 = (const float*)d_in[16];
    const float* g_s2 = (const float*)d_in[17];
    const float* b_s2 = (const float*)d_in[18];
    const int*   nb1  = (const int*)d_in[19];
    const int*   nbs  = (const int*)d_in[20];
    const int*   nb2  = (const int*)d_in[21];
    float* out = (float*)d_out;

    float *A, *B, *C, *D;
    cudaGetSymbolAddress((void**)&A, g_A);
    cudaGetSymbolAddress((void**)&B, g_B);
    cudaGetSymbolAddress((void**)&C, g_C);
    cudaGetSymbolAddress((void**)&D, g_D);
    __nv_bfloat16 *xh, *xl, *Fh, *Fl, *w1h, *w1l, *wbh, *wbl, *w2h, *w2l;
    cudaGetSymbolAddress((void**)&xh, g_xh);
    cudaGetSymbolAddress((void**)&xl, g_xl);
    cudaGetSymbolAddress((void**)&Fh, g_Fh);
    cudaGetSymbolAddress((void**)&Fl, g_Fl);
    cudaGetSymbolAddress((void**)&w1h, g_w1h);
    cudaGetSymbolAddress((void**)&w1l, g_w1l);
    cudaGetSymbolAddress((void**)&wbh, g_wbh);
    cudaGetSymbolAddress((void**)&wbl, g_wbl);
    cudaGetSymbolAddress((void**)&w2h, g_w2h);
    cudaGetSymbolAddress((void**)&w2l, g_w2l);

    constexpr int SM128 = 1024 + 2048 + 2 * (4 * 128 * 128 + 2 * 128 * 128);
    constexpr int SM32  = 1024 + 2048 + 2 * (4 * 128 * 128 + 2 * 32 * 128);
    cudaFuncSetAttribute(spconv_tc<256, 128>, cudaFuncAttributeMaxDynamicSharedMemorySize, SM128);
    cudaFuncSetAttribute(spconv_tc<128, 128>, cudaFuncAttributeMaxDynamicSharedMemorySize, SM128);
    cudaFuncSetAttribute(spconv_tc<128, 32>,  cudaFuncAttributeMaxDynamicSharedMemorySize, SM32);

    const int G1 = M1 / 256;  // 108
    const int G2 = M2 / 256;  // 180
    const int EW_G = 296, EW_T = 256;

    // Launch order: prep(1) conv1(2) apply(3) conv11(4) apply(5) conv12(6)
    // so ncu -s 5 -c 1 profiles spconv_tc<128,128>.
    prep_all<<<512, 256>>>(x, w_s1, w11, w12, w21, w22, w_s2,
                           xh, xl, w1h, w1l, wbh, wbl, w2h, w2l);

    spconv_tc<256, 128><<<G1, 288, SM128>>>(xh, xl, w1h, w1l, nb1, B, M1);
    bn_apply<128, true, false, true, true><<<EW_G, EW_T>>>(B, nullptr, g_s1, b_s1, A, Fh, Fl, M1, G1);

    spconv_tc<128, 128><<<G1, 288, SM128>>>(Fh, Fl, wbh + 0 * WB_SZ, wbl + 0 * WB_SZ, nbs, B, M1);
    bn_apply<128, true, false, true, false><<<EW_G, EW_T>>>(B, nullptr, g11, b11, nullptr, Fh, Fl, M1, G1);

    spconv_tc<128, 128><<<G1, 288, SM128>>>(Fh, Fl, wbh + 1 * WB_SZ, wbl + 1 * WB_SZ, nbs, C, M1);
    bn_apply<128, true, true, true, true><<<EW_G, EW_T>>>(C, A, g12, b12, A, Fh, Fl, M1, G1);

    spconv_tc<128, 128><<<G1, 288, SM128>>>(Fh, Fl, wbh + 2 * WB_SZ, wbl + 2 * WB_SZ, nbs, B, M1);
    bn_apply<128, true, false, true, false><<<EW_G, EW_T>>>(B, nullptr, g21, b21, nullptr, Fh, Fl, M1, G1);

    spconv_tc<128, 128><<<G1, 288, SM128>>>(Fh, Fl, wbh + 3 * WB_SZ, wbl + 3 * WB_SZ, nbs, C, M1);
    bn_apply<128, true, true, true, true><<<EW_G, EW_T>>>(C, A, g22, b22, A, Fh, Fl, M1, G1);

    spconv_tc<128, 32><<<G2, 288, SM32>>>(Fh, Fl, w2h, w2l, nb2, D, M2);
    bn_apply<32, true, false, false, true><<<EW_G, EW_T>>>(D, nullptr, g_s2, b_s2, out, nullptr, nullptr, M2, G2);
}

// round 12
// speedup vs baseline: 1.1246x; 1.1246x over previous
#include <cuda_runtime.h>
#include <cuda_bf16.h>
#include <cstdint>

// ---------------------------------------------------------------------------
// SparseResNet on GB300 — Round 11: warp-specialized tcgen05 bf16x3 conv.
// vs R10: producer loop reordered — arrive full(it) BEFORE issuing gather(it+1)
// so next-iteration gather issue+latency overlaps the current MMA batch.
// Critical-path recurrence then pins the period at the 1536-cyc tensor floor.
// ---------------------------------------------------------------------------

#if defined(__CUDA_ARCH_FEAT_SM103_ALL) || defined(__CUDA_ARCH_FEAT_SM100_ALL) || \
    defined(__CUDA_ARCH_FEAT_SM101_ALL)
#define HAS_TC 1
#else
#define HAS_TC 0
#endif

#define M1 27648
#define M2 46080
#define MAXPART 192

// fp32 masters / scratch
__device__ float g_A[M1 * 128];
__device__ float g_B[M1 * 128];
__device__ float g_C[M1 * 128];
__device__ float g_D[M2 * 32];
__device__ float g_psum[MAXPART * 128];
__device__ float g_pssq[MAXPART * 128];

// split bf16 activations
__device__ __nv_bfloat16 g_xh[9216 * 256];
__device__ __nv_bfloat16 g_xl[9216 * 256];
__device__ __nv_bfloat16 g_Fh[M1 * 128];
__device__ __nv_bfloat16 g_Fl[M1 * 128];

// split + transposed weights: layout [k][cout][cin]
__device__ __nv_bfloat16 g_w1h[27 * 128 * 256];
__device__ __nv_bfloat16 g_w1l[27 * 128 * 256];
#define WB_SZ (27 * 128 * 128)
__device__ __nv_bfloat16 g_wbh[4 * WB_SZ];
__device__ __nv_bfloat16 g_wbl[4 * WB_SZ];
__device__ __nv_bfloat16 g_w2h[27 * 32 * 128];
__device__ __nv_bfloat16 g_w2l[27 * 32 * 128];

// ------------------------------ PTX helpers --------------------------------
__device__ __forceinline__ uint32_t smem_u32(const void* p) {
    uint32_t a;
    asm("{ .reg .u64 t; cvta.to.shared.u64 t, %1; cvt.u32.u64 %0, t; }"
        : "=r"(a) : "l"(p));
    return a;
}

// cp.async 16B with selectable src-size (0 => zero-fill). Ampere+, no 'a' gate.
__device__ __forceinline__ void cp16(uint32_t dst, const void* src, int sz) {
    asm volatile("cp.async.cg.shared.global [%0], [%1], 16, %2;"
                 :: "r"(dst), "l"(src), "r"(sz) : "memory");
}
#define CP_COMMIT() asm volatile("cp.async.commit_group;" ::: "memory")
#define CP_WAIT0()  asm volatile("cp.async.wait_group 0;" ::: "memory")

#if HAS_TC
__device__ __forceinline__ uint32_t elect_one_pred() {
    uint32_t pred;
    asm volatile(
        "{\n\t.reg .pred p;\n\t"
        "elect.sync _|p, 0xFFFFFFFF;\n\t"
        "selp.b32 %0, 1, 0, p;\n\t}"
        : "=r"(pred));
    return pred;
}

#define TC_ALLOC(sa, n)                                                      \
    asm volatile("tcgen05.alloc.cta_group::1.sync.aligned.shared::cta.b32 [%0], %1;" \
                 :: "r"(sa), "r"((uint32_t)(n)) : "memory")
#define TC_DEALLOC(t, n)                                                     \
    asm volatile("tcgen05.dealloc.cta_group::1.sync.aligned.b32 %0, %1;"     \
                 :: "r"(t), "r"((uint32_t)(n)))
#define TC_COMMIT(mb)                                                        \
    asm volatile("tcgen05.commit.cta_group::1.mbarrier::arrive::one.shared::cluster.b64 [%0];" \
                 :: "r"(mb) : "memory")
#define TC_WAIT_LD() asm volatile("tcgen05.wait::ld.sync.aligned;" ::: "memory")
#define TC_FENCE_AFTER() asm volatile("tcgen05.fence::after_thread_sync;" ::: "memory")
#define FENCE_ASYNC() asm volatile("fence.proxy.async.shared::cta;" ::: "memory")

#define MB_INIT(a, c)                                                        \
    asm volatile("mbarrier.init.shared.b64 [%0], %1;" :: "r"(a), "r"((uint32_t)(c)) : "memory")
#define MB_INVAL(a)                                                          \
    asm volatile("mbarrier.inval.shared.b64 [%0];" :: "r"(a) : "memory")
#define MB_ARRIVE(a)                                                         \
    asm volatile("mbarrier.arrive.shared.b64 _, [%0];" :: "r"(a) : "memory")

__device__ __forceinline__ void mb_wait(uint32_t mbar, uint32_t parity) {
    uint32_t done;
    asm volatile(
        "{\n\t.reg .pred p;\n\t"
        "mbarrier.try_wait.parity.acquire.cta.shared::cta.b64 p, [%1], %2;\n\t"
        "selp.b32 %0, 1, 0, p;\n\t}"
        : "=r"(done) : "r"(mbar), "r"(parity) : "memory");
    if (!done) {
        asm volatile(
            "{\n\t.reg .pred P1;\n\t"
            "WL_%=:\n\t"
            "mbarrier.try_wait.parity.acquire.cta.shared::cta.b64 P1, [%0], %1, 0x989680;\n\t"
            "@P1 bra.uni WD_%=;\n\t"
            "bra.uni WL_%=;\n\t"
            "WD_%=:\n\t}"
            :: "r"(mbar), "r"(parity) : "memory");
    }
}

// SS-mode bf16 MMA, fp32 accumulate, cta_group::1
__device__ __forceinline__ void mma_bf16_ss(uint32_t d, uint64_t ad, uint64_t bd,
                                            uint32_t id, uint32_t en) {
    asm volatile(
        "{\n\t.reg .pred p;\n\t"
        "setp.ne.u32 p, %5, 0;\n\t"
        "tcgen05.mma.cta_group::1.kind::f16 [%0], %1, %2, %3, {%4, %4, %4, %4}, p;\n\t}"
        :: "r"(d), "l"(ad), "l"(bd), "r"(id), "r"(0u), "r"(en) : "memory");
}

__device__ __forceinline__ void tc_ld32(uint32_t* r, uint32_t ta) {
    asm volatile(
        "tcgen05.ld.sync.aligned.32x32b.x32.b32 "
        "{%0, %1, %2, %3, %4, %5, %6, %7, "
        " %8, %9, %10, %11, %12, %13, %14, %15, "
        " %16, %17, %18, %19, %20, %21, %22, %23, "
        " %24, %25, %26, %27, %28, %29, %30, %31}, [%32];"
        : "=r"(r[0]), "=r"(r[1]), "=r"(r[2]), "=r"(r[3]),
          "=r"(r[4]), "=r"(r[5]), "=r"(r[6]), "=r"(r[7]),
          "=r"(r[8]), "=r"(r[9]), "=r"(r[10]), "=r"(r[11]),
          "=r"(r[12]), "=r"(r[13]), "=r"(r[14]), "=r"(r[15]),
          "=r"(r[16]), "=r"(r[17]), "=r"(r[18]), "=r"(r[19]),
          "=r"(r[20]), "=r"(r[21]), "=r"(r[22]), "=r"(r[23]),
          "=r"(r[24]), "=r"(r[25]), "=r"(r[26]), "=r"(r[27]),
          "=r"(r[28]), "=r"(r[29]), "=r"(r[30]), "=r"(r[31])
        : "r"(ta));
}
#endif  // HAS_TC

#define SW128(o) ((o) ^ (((o) >> 3) & 0x70))

// SW128 K-major descriptor (validated: layout=2, ver=1, SBO=64, LBO=1)
#define DBASE ((2ull << 61) | (1ull << 46) | (64ull << 32) | (1ull << 16))
#define MKDESC(a) (DBASE | (uint64_t)((((a) >> 4)) & 0x3FFF))

// ---------------------------------------------------------------------------
// Warp-specialized tcgen05 implicit-gather conv. 2 M-tiles per CTA (256 rows),
// K chunked at 64, 288 threads: warps 0-7 = cp.async producers, warp 8 = MMA
// issuer. Producer loop: CP_WAIT0 -> fence -> bar -> arrive full -> wait done
// -> issue next gather (gather overlaps MMA fully). BN partials in epilogue.
// ---------------------------------------------------------------------------
template <int CIN, int COUT>
__global__ void __launch_bounds__(288, 1)
spconv_tc(const __nv_bfloat16* __restrict__ fh, const __nv_bfloat16* __restrict__ fl,
          const __nv_bfloat16* __restrict__ wh, const __nv_bfloat16* __restrict__ wl,
          const int* __restrict__ nb, float* __restrict__ out, int M) {
#if HAS_TC
    extern __shared__ __align__(16) char smem[];
    constexpr int A_T     = 128 * 128;
    constexpr int A_BYTES = 4 * A_T;
    constexpr int B_ONE   = COUT * 128;
    constexpr int STAGE   = A_BYTES + 2 * B_ONE;
    constexpr int CHUNKS  = CIN / 64;
    constexpr int NIT     = 27 * CHUNKS;
    constexpr int WITER   = COUT * 8 / 256;
    constexpr uint32_t IDESC =
        (1u << 4) | (1u << 7) | (1u << 10) | ((uint32_t)(COUT / 8) << 17) | (8u << 24);

    const int tid = threadIdx.x;
    const int wid = tid >> 5;
    const int lid = tid & 31;
    const int m0  = blockIdx.x * 256;

    uint32_t b32 = smem_u32(smem);
    uint32_t pad = (1024u - (b32 & 1023u)) & 1023u;
    char* ctrl   = smem + pad;
    char* tiles  = ctrl + 2048;
    uint32_t ctrl_a  = b32 + pad;
    uint32_t tiles_a = ctrl_a + 2048;
    uint32_t mb_done[2] = {ctrl_a + 8,  ctrl_a + 16};
    uint32_t mb_full[2] = {ctrl_a + 24, ctrl_a + 32};

    if (wid == 0) TC_ALLOC(ctrl_a, 256);
    if (tid == 0) {
        MB_INIT(mb_done[0], 1); MB_INIT(mb_done[1], 1);
        MB_INIT(mb_full[0], 1); MB_INIT(mb_full[1], 1);
    }
    __syncthreads();
    const uint32_t tmem = *(volatile uint32_t*)ctrl;

    if (wid < 8) {
        // ---------------- producers (256 threads): pipelined cp.async -------
        int gro[8];
        uint32_t adst[8];
        uint32_t asrcseg[8];
#pragma unroll
        for (int i = 0; i < 8; ++i) {
            int t = tid + 256 * i;
            int tile = t >> 10, row = (t >> 3) & 127, seg = t & 7;
            gro[i]     = m0 + tile * 128 + row;
            adst[i]    = tile * (2 * A_T) + SW128(row * 128 + seg * 16);
            asrcseg[i] = seg * 16;
        }
        int ridx[8];
#pragma unroll
        for (int i = 0; i < 8; ++i) ridx[i] = nb[gro[i]];   // k = 0

        auto issue_gather = [&](uint32_t sbase, int k, int c0) {
#pragma unroll
            for (int i = 0; i < 8; ++i) {
                int idx = ridx[i];
                int sz  = (idx >= 0) ? 16 : 0;
                int ri  = (idx >= 0) ? idx : 0;
                const char* ph = (const char*)(fh + (size_t)ri * CIN + c0) + asrcseg[i];
                const char* pl = (const char*)(fl + (size_t)ri * CIN + c0) + asrcseg[i];
                uint32_t dst = sbase + adst[i];
                cp16(dst, ph, sz);
                cp16(dst + A_T, pl, sz);
            }
#pragma unroll
            for (int i = 0; i < WITER; ++i) {
                int t = tid + 256 * i;
                int row = t >> 3, seg = t & 7;
                const char* ph = (const char*)(wh + ((size_t)k * COUT + row) * CIN + c0) + seg * 16;
                const char* pl = (const char*)(wl + ((size_t)k * COUT + row) * CIN + c0) + seg * 16;
                uint32_t so = SW128(row * 128 + seg * 16);
                uint32_t dst = sbase + A_BYTES + so;
                cp16(dst, ph, 16);
                cp16(dst + B_ONE, pl, 16);
            }
            CP_COMMIT();
        };

        issue_gather(tiles_a, 0, 0);   // prologue: iteration 0 into buffer 0

        for (int it = 0; it < NIT; ++it) {
            const int b = it & 1;
            // gather(it) is the ONLY outstanding group here
            CP_WAIT0();
            FENCE_ASYNC();
            asm volatile("bar.sync 1, 256;" ::: "memory");
            if (tid == 0) MB_ARRIVE(mb_full[b]);     // MMA(it) can start NOW

            if (it + 1 < NIT) {
                const int k1 = (it + 1) / CHUNKS;
                const int c1 = ((it + 1) % CHUNKS) * 64;
                if ((it + 1) % CHUNKS == 0) {
#pragma unroll
                    for (int i = 0; i < 8; ++i) ridx[i] = nb[k1 * M + gro[i]];
                }
                // buffer (it+1)&1 free once MMA(it-1) is complete
                if (it >= 1) mb_wait(mb_done[(it + 1) & 1], (uint32_t)(((it - 1) >> 1) & 1));
                issue_gather(tiles_a + (uint32_t)(((it + 1) & 1) * STAGE), k1, c1);
            }
        }
    } else {
        // ---------------- consumer (warp 8): pure MMA issuer ----------------
        for (int it = 0; it < NIT; ++it) {
            const int b = it & 1;
            mb_wait(mb_full[b], (uint32_t)((it >> 1) & 1));
            if (elect_one_pred()) {
                const uint32_t sbase = tiles_a + (uint32_t)(b * STAGE);
                uint64_t bdh = MKDESC(sbase + A_BYTES);
                uint64_t bdl = MKDESC(sbase + A_BYTES + B_ONE);
#pragma unroll
                for (int tile = 0; tile < 2; ++tile) {
                    uint64_t adh = MKDESC(sbase + tile * (2 * A_T));
                    uint64_t adl = MKDESC(sbase + tile * (2 * A_T) + A_T);
                    uint32_t dt  = tmem + tile * 128;
#pragma unroll
                    for (int s = 0; s < 4; ++s) {
                        mma_bf16_ss(dt, adh + 2 * s, bdh + 2 * s, IDESC,
                                    (it == 0 && s == 0) ? 0u : 1u);
                        mma_bf16_ss(dt, adh + 2 * s, bdl + 2 * s, IDESC, 1u);
                        mma_bf16_ss(dt, adl + 2 * s, bdh + 2 * s, IDESC, 1u);
                    }
                }
                TC_COMMIT(mb_done[b]);
            }
        }
    }

    // drain both buffers' last MMA commits
    {
        uint32_t up = (uint32_t)((NIT / 2 - 1) & 1);
        mb_wait(mb_done[0], up);
        mb_wait(mb_done[1], up);
    }
    __syncthreads();
    TC_FENCE_AFTER();

    // epilogue (warps 0-7): store D + per-CTA BN partials
    float* ssum = reinterpret_cast<float*>(tiles);
    float* ssq  = ssum + 8 * COUT;
    if (wid < 8) {
        int tile = wid >> 2, sub = wid & 3;
        int row  = m0 + tile * 128 + sub * 32 + lid;
        uint32_t tbase = tmem + tile * 128;
        float* op = out + (size_t)row * COUT;
        uint32_t r[32];
#pragma unroll
        for (int c = 0; c < COUT; c += 32) {
            tc_ld32(r, tbase + c);
            TC_WAIT_LD();
#pragma unroll
            for (int j = 0; j < 32; j += 4)
                *reinterpret_cast<float4*>(op + c + j) =
                    make_float4(__uint_as_float(r[j]), __uint_as_float(r[j + 1]),
                                __uint_as_float(r[j + 2]), __uint_as_float(r[j + 3]));
#pragma unroll
            for (int j = 0; j < 32; ++j) {
                float v = __uint_as_float(r[j]);
                float s = v, q = v * v;
#pragma unroll
                for (int o = 16; o > 0; o >>= 1) {
                    s += __shfl_xor_sync(0xFFFFFFFFu, s, o);
                    q += __shfl_xor_sync(0xFFFFFFFFu, q, o);
                }
                if (lid == 0) { ssum[wid * COUT + c + j] = s; ssq[wid * COUT + c + j] = q; }
            }
        }
    }
    __syncthreads();
    if (tid < COUT) {
        float s = 0.f, q = 0.f;
#pragma unroll
        for (int w = 0; w < 8; ++w) { s += ssum[w * COUT + tid]; q += ssq[w * COUT + tid]; }
        g_psum[blockIdx.x * COUT + tid] = s;
        g_pssq[blockIdx.x * COUT + tid] = q;
    }

    __syncthreads();
    if (tid == 0) {
        MB_INVAL(mb_done[0]); MB_INVAL(mb_done[1]);
        MB_INVAL(mb_full[0]); MB_INVAL(mb_full[1]);
    }
    if (wid == 0) TC_DEALLOC(tmem, 256);
#else
    // --- SIMT fallback (non-'a' PTX stage only; correct, slow) ---
    const int m0 = blockIdx.x * 256;
    for (int o = threadIdx.x; o < 256 * COUT; o += (int)blockDim.x) {
        int r = o / COUT, c = o % COUT;
        float acc = 0.f;
        for (int k = 0; k < 27; ++k) {
            int idx = nb[k * M + m0 + r];
            if (idx < 0) continue;
            const __nv_bfloat16* ph = fh + (size_t)idx * CIN;
            const __nv_bfloat16* pl = fl + (size_t)idx * CIN;
            const __nv_bfloat16* qh = wh + ((size_t)k * COUT + c) * CIN;
            const __nv_bfloat16* ql = wl + ((size_t)k * COUT + c) * CIN;
            for (int ci = 0; ci < CIN; ++ci) {
                float a = __bfloat162float(ph[ci]) + __bfloat162float(pl[ci]);
                float w = __bfloat162float(qh[ci]) + __bfloat162float(ql[ci]);
                acc = fmaf(a, w, acc);
            }
        }
        out[(size_t)(m0 + r) * COUT + c] = acc;
    }
    __syncthreads();
    if (threadIdx.x < COUT) {
        float s = 0.f, q = 0.f;
        for (int r = 0; r < 256; ++r) {
            float v = out[(size_t)(m0 + r) * COUT + threadIdx.x];
            s += v; q += v * v;
        }
        g_psum[blockIdx.x * COUT + threadIdx.x] = s;
        g_pssq[blockIdx.x * COUT + threadIdx.x] = q;
    }
#endif
}

// --------------------- fused prep: split x + all weights -------------------
__global__ void prep_all(const float* __restrict__ x,
                         const float* w1, const float* w11, const float* w12,
                         const float* w21, const float* w22, const float* w2,
                         __nv_bfloat16* xh, __nv_bfloat16* xl,
                         __nv_bfloat16* w1h, __nv_bfloat16* w1l,
                         __nv_bfloat16* wbh, __nv_bfloat16* wbl,
                         __nv_bfloat16* w2h, __nv_bfloat16* w2l) {
    const int NX = 9216 * 256;
    const int N1 = 27 * 256 * 128;
    const int NB = 27 * 128 * 128;
    const int N2 = 27 * 128 * 32;
    const int TOT = NX + N1 + 4 * NB + N2;
    for (int t = blockIdx.x * blockDim.x + threadIdx.x; t < TOT;
         t += gridDim.x * blockDim.x) {
        if (t < NX) {
            float v = x[t];
            __nv_bfloat16 h = __float2bfloat16_rn(v);
            xh[t] = h;
            xl[t] = __float2bfloat16_rn(v - __bfloat162float(h));
            continue;
        }
        int u = t - NX;
        const float* src; __nv_bfloat16 *oh, *ol; int CI, CO, li;
        if (u < N1) { src = w1; oh = w1h; ol = w1l; CI = 256; CO = 128; li = u; }
        else if (u < N1 + 4 * NB) {
            int q = (u - N1) / NB, r = (u - N1) % NB;
            src = (q == 0) ? w11 : (q == 1) ? w12 : (q == 2) ? w21 : w22;
            oh = wbh + q * NB; ol = wbl + q * NB; CI = 128; CO = 128; li = r;
        } else { src = w2; oh = w2h; ol = w2l; CI = 128; CO = 32; li = u - N1 - 4 * NB; }
        int k = li / (CI * CO), r = li % (CI * CO);
        int ci = r / CO, co = r % CO;
        float v = src[li];
        __nv_bfloat16 h = __float2bfloat16_rn(v);
        int o = (k * CO + co) * CI + ci;
        oh[o] = h;
        ol[o] = __float2bfloat16_rn(v - __bfloat162float(h));
    }
}

// ---------------- fused BN finalize + normalize (+res)(+relu)(+split) ------
template <int C, bool RELU, bool RES, bool SPLIT, bool WF32>
__global__ void bn_apply(const float* __restrict__ f, const float* __restrict__ res,
                         const float* __restrict__ g, const float* __restrict__ b,
                         float* __restrict__ out, __nv_bfloat16* __restrict__ oh,
                         __nv_bfloat16* __restrict__ ol, int M, int npart) {
    __shared__ float sc[C], sh[C];
    for (int c = threadIdx.x; c < C; c += blockDim.x) {
        float s = 0.f, ss = 0.f;
        for (int i = 0; i < npart; ++i) { s += g_psum[i * C + c]; ss += g_pssq[i * C + c]; }
        float inv_m = 1.f / (float)M;
        float mu  = s * inv_m;
        float var = ss * inv_m - mu * mu;
        float scv = g[c] * rsqrtf(var + 1e-5f);
        sc[c] = scv;
        sh[c] = b[c] - mu * scv;
    }
    __syncthreads();
    int total4 = M * C / 4;
    for (int i = blockIdx.x * blockDim.x + threadIdx.x; i < total4;
         i += gridDim.x * blockDim.x) {
        float4 v = reinterpret_cast<const float4*>(f)[i];
        int c0 = (i * 4) % C;
        v.x = v.x * sc[c0 + 0] + sh[c0 + 0];
        v.y = v.y * sc[c0 + 1] + sh[c0 + 1];
        v.z = v.z * sc[c0 + 2] + sh[c0 + 2];
        v.w = v.w * sc[c0 + 3] + sh[c0 + 3];
        if (RES) {
            float4 r = reinterpret_cast<const float4*>(res)[i];
            v.x += r.x; v.y += r.y; v.z += r.z; v.w += r.w;
        }
        if (RELU) {
            v.x = fmaxf(v.x, 0.f); v.y = fmaxf(v.y, 0.f);
            v.z = fmaxf(v.z, 0.f); v.w = fmaxf(v.w, 0.f);
        }
        if (WF32) reinterpret_cast<float4*>(out)[i] = v;
        if (SPLIT) {
            __nv_bfloat16 hx = __float2bfloat16_rn(v.x), hy = __float2bfloat16_rn(v.y);
            __nv_bfloat16 hz = __float2bfloat16_rn(v.z), hw = __float2bfloat16_rn(v.w);
            __nv_bfloat162* oh2 = reinterpret_cast<__nv_bfloat162*>(oh);
            __nv_bfloat162* ol2 = reinterpret_cast<__nv_bfloat162*>(ol);
            oh2[2 * i]     = __nv_bfloat162(hx, hy);
            oh2[2 * i + 1] = __nv_bfloat162(hz, hw);
            ol2[2 * i]     = __nv_bfloat162(__float2bfloat16_rn(v.x - __bfloat162float(hx)),
                                            __float2bfloat16_rn(v.y - __bfloat162float(hy)));
            ol2[2 * i + 1] = __nv_bfloat162(__float2bfloat16_rn(v.z - __bfloat162float(hz)),
                                            __float2bfloat16_rn(v.w - __bfloat162float(hw)));
        }
    }
}

// ---------------------------------------------------------------------------
extern "C" void kernel_launch(void* const* d_in, const int* in_sizes, int n_in,
                              void* d_out, int out_size) {
    (void)in_sizes; (void)n_in; (void)out_size;

    const float* x    = (const float*)d_in[0];
    const float* w_s1 = (const float*)d_in[1];
    const float* g_s1 = (const float*)d_in[2];
    const float* b_s1 = (const float*)d_in[3];
    const float* w11  = (const float*)d_in[4];
    const float* g11  = (const float*)d_in[5];
    const float* b11  = (const float*)d_in[6];
    const float* w12  = (const float*)d_in[7];
    const float* g12  = (const float*)d_in[8];
    const float* b12  = (const float*)d_in[9];
    const float* w21  = (const float*)d_in[10];
    const float* g21  = (const float*)d_in[11];
    const float* b21  = (const float*)d_in[12];
    const float* w22  = (const float*)d_in[13];
    const float* g22  = (const float*)d_in[14];
    const float* b22  = (const float*)d_in[15];
    const float* w_s2 = (const float*)d_in[16];
    const float* g_s2 = (const float*)d_in[17];
    const float* b_s2 = (const float*)d_in[18];
    const int*   nb1  = (const int*)d_in[19];
    const int*   nbs  = (const int*)d_in[20];
    const int*   nb2  = (const int*)d_in[21];
    float* out = (float*)d_out;

    float *A, *B, *C, *D;
    cudaGetSymbolAddress((void**)&A, g_A);
    cudaGetSymbolAddress((void**)&B, g_B);
    cudaGetSymbolAddress((void**)&C, g_C);
    cudaGetSymbolAddress((void**)&D, g_D);
    __nv_bfloat16 *xh, *xl, *Fh, *Fl, *w1h, *w1l, *wbh, *wbl, *w2h, *w2l;
    cudaGetSymbolAddress((void**)&xh, g_xh);
    cudaGetSymbolAddress((void**)&xl, g_xl);
    cudaGetSymbolAddress((void**)&Fh, g_Fh);
    cudaGetSymbolAddress((void**)&Fl, g_Fl);
    cudaGetSymbolAddress((void**)&w1h, g_w1h);
    cudaGetSymbolAddress((void**)&w1l, g_w1l);
    cudaGetSymbolAddress((void**)&wbh, g_wbh);
    cudaGetSymbolAddress((void**)&wbl, g_wbl);
    cudaGetSymbolAddress((void**)&w2h, g_w2h);
    cudaGetSymbolAddress((void**)&w2l, g_w2l);

    constexpr int SM128 = 1024 + 2048 + 2 * (4 * 128 * 128 + 2 * 128 * 128);
    constexpr int SM32  = 1024 + 2048 + 2 * (4 * 128 * 128 + 2 * 32 * 128);
    cudaFuncSetAttribute(spconv_tc<256, 128>, cudaFuncAttributeMaxDynamicSharedMemorySize, SM128);
    cudaFuncSetAttribute(spconv_tc<128, 128>, cudaFuncAttributeMaxDynamicSharedMemorySize, SM128);
    cudaFuncSetAttribute(spconv_tc<128, 32>,  cudaFuncAttributeMaxDynamicSharedMemorySize, SM32);

    const int G1 = M1 / 256;  // 108
    const int G2 = M2 / 256;  // 180
    const int EW_G = 296, EW_T = 256;

    // Launch order: prep(1) conv1(2) apply(3) conv11(4) apply(5) conv12(6)
    // so ncu -s 5 -c 1 profiles spconv_tc<128,128>.
    prep_all<<<512, 256>>>(x, w_s1, w11, w12, w21, w22, w_s2,
                           xh, xl, w1h, w1l, wbh, wbl, w2h, w2l);

    spconv_tc<256, 128><<<G1, 288, SM128>>>(xh, xl, w1h, w1l, nb1, B, M1);
    bn_apply<128, true, false, true, true><<<EW_G, EW_T>>>(B, nullptr, g_s1, b_s1, A, Fh, Fl, M1, G1);

    spconv_tc<128, 128><<<G1, 288, SM128>>>(Fh, Fl, wbh + 0 * WB_SZ, wbl + 0 * WB_SZ, nbs, B, M1);
    bn_apply<128, true, false, true, false><<<EW_G, EW_T>>>(B, nullptr, g11, b11, nullptr, Fh, Fl, M1, G1);

    spconv_tc<128, 128><<<G1, 288, SM128>>>(Fh, Fl, wbh + 1 * WB_SZ, wbl + 1 * WB_SZ, nbs, C, M1);
    bn_apply<128, true, true, true, true><<<EW_G, EW_T>>>(C, A, g12, b12, A, Fh, Fl, M1, G1);

    spconv_tc<128, 128><<<G1, 288, SM128>>>(Fh, Fl, wbh + 2 * WB_SZ, wbl + 2 * WB_SZ, nbs, B, M1);
    bn_apply<128, true, false, true, false><<<EW_G, EW_T>>>(B, nullptr, g21, b21, nullptr, Fh, Fl, M1, G1);

    spconv_tc<128, 128><<<G1, 288, SM128>>>(Fh, Fl, wbh + 3 * WB_SZ, wbl + 3 * WB_SZ, nbs, C, M1);
    bn_apply<128, true, true, true, true><<<EW_G, EW_T>>>(C, A, g22, b22, A, Fh, Fl, M1, G1);

    spconv_tc<128, 32><<<G2, 288, SM32>>>(Fh, Fl, w2h, w2l, nb2, D, M2);
    bn_apply<32, true, false, false, true><<<EW_G, EW_T>>>(D, nullptr, g_s2, b_s2, out, nullptr, nullptr, M2, G2);
}